// round 7
// baseline (speedup 1.0000x reference)
#include <cuda_runtime.h>
#include <cuda_fp16.h>
#include <cstdint>
#include <cstddef>

// ---------------- problem constants ----------------
#define T_TOK 32768
#define DIM   512
#define HID   2048
#define NEXP  8
#define TOPK  2
#define MAXMB 520                      // max total m-blocks: 512 + 8 (ceil slack)

// ---------------- GEMM tiling ----------------
#define TILE_M   128
#define TILE_N   128
#define CHUNK_K  64                    // fp16 elements per K-chunk = 128 bytes
#define NSTAGE   3
#define NT_ITER  2                     // n-tiles per CTA, pipelined across the boundary
#define ATILE_B  (TILE_M * 128)        // 16 KB
#define STAGE_B  (2 * ATILE_B)         // A + B = 32 KB
#define SMEM_BYTES (NSTAGE * STAGE_B)  // 96 KB -> 2 CTAs/SM

// ---------------- device scratch (allocation-free rule: __device__ globals) ----------------
__device__ __align__(256) __half g_xh [T_TOK * DIM];                 // fp16 tokens
__device__ __align__(256) __half g_w1h[NEXP * HID * DIM];            // fp16 w1
__device__ __align__(256) __half g_w2h[NEXP * DIM * HID];            // fp16 w2
__device__ __align__(256) __half g_h  [(size_t)T_TOK * TOPK * HID];  // gathered hidden (relu'd)
__device__ __align__(256) __half g_y  [(size_t)T_TOK * TOPK * DIM];  // per-row expert output (fp16)
__device__ int   g_cnt[NEXP];
__device__ int   g_off[NEXP];
__device__ int   g_boff[NEXP + 1];            // m-block prefix per expert
__device__ int   g_gather[NEXP * T_TOK];      // expert -> token list
__device__ int   g_etok[T_TOK * TOPK];        // token -> expert ids
__device__ int   g_ptok[T_TOK * TOPK];        // token -> position within expert list
__device__ float g_wtok[T_TOK * TOPK];        // token -> softmax weights

// ---------------- PTX helpers (all baseline sm_80+ instructions) ----------------
__device__ __forceinline__ uint32_t smem_u32(const void* p) {
    uint32_t a;
    asm("{ .reg .u64 t; cvta.to.shared.u64 t, %1; cvt.u32.u64 %0, t; }" : "=r"(a) : "l"(p));
    return a;
}

__device__ __forceinline__ void cpa16(uint32_t dst, const void* src, unsigned srcsz) {
    asm volatile("cp.async.cg.shared.global [%0], [%1], 16, %2;"
                 :: "r"(dst), "l"(src), "r"(srcsz) : "memory");
}

__device__ __forceinline__ void ldsm4(uint32_t* r, uint32_t addr) {
    asm volatile("ldmatrix.sync.aligned.m8n8.x4.shared.b16 {%0,%1,%2,%3}, [%4];"
                 : "=r"(r[0]), "=r"(r[1]), "=r"(r[2]), "=r"(r[3]) : "r"(addr));
}

__device__ __forceinline__ void mma16816(float* c, const uint32_t* a, const uint32_t* b) {
    asm volatile("mma.sync.aligned.m16n8k16.row.col.f32.f16.f16.f32 "
                 "{%0,%1,%2,%3}, {%4,%5,%6,%7}, {%8,%9}, {%0,%1,%2,%3};"
                 : "+f"(c[0]), "+f"(c[1]), "+f"(c[2]), "+f"(c[3])
                 : "r"(a[0]), "r"(a[1]), "r"(a[2]), "r"(a[3]), "r"(b[0]), "r"(b[1]));
}

__device__ __forceinline__ uint32_t h2u(__half2 h) {
    uint32_t u;
    *(__half2*)&u = h;
    return u;
}

// ---------------- tiny kernels ----------------
__global__ void init_kernel() {
    if (threadIdx.x < NEXP) g_cnt[threadIdx.x] = 0;
}

__global__ void scan_kernel() {
    if (threadIdx.x == 0) {
        int a = 0, b = 0;
        for (int e = 0; e < NEXP; e++) {
            g_off[e] = a;  g_boff[e] = b;
            a += g_cnt[e]; b += (g_cnt[e] + TILE_M - 1) / TILE_M;
        }
        g_boff[NEXP] = b;
    }
}

__global__ void cvtw_kernel(const float* __restrict__ w1, const float* __restrict__ w2) {
    size_t n = (size_t)NEXP * HID * DIM / 4;
    const float4* w1v = (const float4*)w1;
    const float4* w2v = (const float4*)w2;
    for (size_t i = (size_t)blockIdx.x * blockDim.x + threadIdx.x; i < n;
         i += (size_t)gridDim.x * blockDim.x) {
        float4 a = w1v[i], b = w2v[i];
        ((uint2*)g_w1h)[i] = make_uint2(h2u(__floats2half2_rn(a.x, a.y)),
                                        h2u(__floats2half2_rn(a.z, a.w)));
        ((uint2*)g_w2h)[i] = make_uint2(h2u(__floats2half2_rn(b.x, b.y)),
                                        h2u(__floats2half2_rn(b.z, b.w)));
    }
}

// gate: fp32 logits, top-2, softmax. Also emits fp16 x. 8 warps = 8 tokens per block.
__global__ void gate_kernel(const float* __restrict__ x, const float* __restrict__ gw) {
    __shared__ float s_gw[NEXP * DIM];
    for (int i = threadIdx.x; i < NEXP * DIM; i += blockDim.x) s_gw[i] = gw[i];
    __syncthreads();
    int w = threadIdx.x >> 5, lane = threadIdx.x & 31;
    int t = blockIdx.x * 8 + w;
    const float* xr = x + (size_t)t * DIM;
    float xv[16];
#pragma unroll
    for (int i = 0; i < 16; i++) xv[i] = xr[lane + 32 * i];
#pragma unroll
    for (int i = 0; i < 16; i++)
        g_xh[(size_t)t * DIM + lane + 32 * i] = __float2half_rn(xv[i]);
    float acc[NEXP];
#pragma unroll
    for (int e = 0; e < NEXP; e++) {
        float a = 0.f;
#pragma unroll
        for (int i = 0; i < 16; i++) a += xv[i] * s_gw[e * DIM + lane + 32 * i];
        acc[e] = a;
    }
#pragma unroll
    for (int off = 16; off > 0; off >>= 1)
#pragma unroll
        for (int e = 0; e < NEXP; e++) acc[e] += __shfl_xor_sync(0xffffffffu, acc[e], off);
    if (lane == 0) {
        int e0 = 0; float l0 = acc[0];
#pragma unroll
        for (int e = 1; e < NEXP; e++) if (acc[e] > l0) { l0 = acc[e]; e0 = e; }
        int e1 = -1; float l1 = -3.4e38f;
#pragma unroll
        for (int e = 0; e < NEXP; e++) if (e != e0 && acc[e] > l1) { l1 = acc[e]; e1 = e; }
        float p1 = expf(l1 - l0);
        float inv = 1.f / (1.f + p1);
        float w0 = inv, w1v = p1 * inv;
        int pos0 = atomicAdd(&g_cnt[e0], 1);
        int pos1 = atomicAdd(&g_cnt[e1], 1);
        g_gather[e0 * T_TOK + pos0] = t;
        g_gather[e1 * T_TOK + pos1] = t;
        g_etok[2 * t] = e0;  g_etok[2 * t + 1] = e1;
        g_ptok[2 * t] = pos0; g_ptok[2 * t + 1] = pos1;
        g_wtok[2 * t] = w0;  g_wtok[2 * t + 1] = w1v;
    }
}

// ---------------- grouped GEMM via mma.sync (HMMA path; tcgen05 rejected by
// compute_100 PTX target the harness uses) ----------------
// G1: h[rows, HID-tile] = relu( gathered_x[rows, DIM] @ w1[e]^T ), fp16 out
// G2: y[rows, DIM-tile] =        h[rows, HID]        @ w2[e]^T  , fp16 out
// CTA tile 128x128xK, 256 threads, warp grid 2(M) x 4(N), warp tile 64x32.
// Each CTA processes NT_ITER consecutive n-tiles with ONE continuous cp.async
// pipeline: loads for tile j+1 are already in flight while tile j's epilogue
// (registers + STG only) runs, so the pipe never drains at tile boundaries.
template <bool G1>
__global__ void __launch_bounds__(256, 2) moe_gemm_kernel() {
    constexpr int KTOT  = G1 ? DIM : HID;
    constexpr int NCH   = KTOT / CHUNK_K;       // 8 or 32 (power of two)
    constexpr int TOTCH = NT_ITER * NCH;
    const int mb = blockIdx.x;
    if (mb >= g_boff[NEXP]) return;
    int e = 0;
#pragma unroll
    for (int k = 1; k < NEXP; k++) if (mb >= g_boff[k]) e = k;
    const int m0     = (mb - g_boff[e]) * TILE_M;
    const int cnt    = g_cnt[e];
    const int off    = g_off[e];
    const int ntBase = blockIdx.y * NT_ITER * TILE_N;

    extern __shared__ char smem[];
    const uint32_t sb = smem_u32(smem);
    const int tid = threadIdx.x, wid = tid >> 5, lane = tid & 31;
    const int wm = wid & 1, wn = wid >> 1;              // warp coords: 2(M) x 4(N)

    const int valid = min(cnt - m0, TILE_M);

    // ---- load mapping: thread t -> row t/2, four 16B segments ----
    const int lr = tid >> 1;                            // 0..127
    const int sseg = (tid & 1) * 4;                     // 0 or 4
    const unsigned asz = (lr < valid) ? 16u : 0u;       // zero-fill invalid rows
    const int ar = min(lr, valid - 1);
    const char* aBase;
    if (G1) {
        int tok = g_gather[e * T_TOK + m0 + ar];
        aBase = (const char*)(g_xh + (size_t)tok * DIM);
    } else {
        aBase = (const char*)(g_h + (size_t)(off + m0 + ar) * HID);
    }
    // B base for the first n-tile of this CTA; +TILE_STRIDE_B bytes per n-tile.
    const char* bBase0 = G1
        ? (const char*)(g_w1h + ((size_t)e * HID + ntBase + lr) * DIM)
        : (const char*)(g_w2h + ((size_t)e * DIM + ntBase + lr) * HID);
    constexpr size_t TILE_STRIDE_B = (size_t)TILE_N * KTOT * 2;
    const int rowoff = lr * 128;
    const int swr = (lr & 7);

    // c = global chunk index: n-tile = c / NCH, k-chunk = c % NCH
    auto load_stage = [&](int stg, int c) {
        const int ch = c & (NCH - 1);
        const char* bp = bBase0 + (size_t)(c >> (G1 ? 3 : 5)) * TILE_STRIDE_B + ch * 128;
        const char* ap = aBase + ch * 128;
        uint32_t s0 = sb + stg * STAGE_B;
#pragma unroll
        for (int i = 0; i < 4; i++) {
            int s = sseg + i;
            uint32_t sw = rowoff + (((unsigned)(s ^ swr)) << 4);
            cpa16(s0 + sw,            ap + s * 16, asz);
            cpa16(s0 + ATILE_B + sw,  bp + s * 16, 16u);
        }
        asm volatile("cp.async.commit_group;" ::: "memory");
    };

#pragma unroll
    for (int i = 0; i < NSTAGE - 1; i++) load_stage(i, i);

    float acc[4][4][4];
#pragma unroll
    for (int a = 0; a < 4; a++)
#pragma unroll
        for (int b = 0; b < 4; b++)
#pragma unroll
            for (int c = 0; c < 4; c++) acc[a][b][c] = 0.f;

    // ldmatrix lane addressing
    const int arow = wm * 64 + (lane & 15);             // A row within tile
    const int akb  = (lane & 16);                       // +16B for k8..15 halves
    const int brow = wn * 32 + (lane & 7) + ((lane & 16) >> 1);
    const int bkb  = ((lane & 8) << 1);

    const int qrow = lane >> 2, qcol = (lane & 3) * 2;

    for (int c = 0; c < TOTCH; c++) {
        // stage c must be complete; stage c+1 may remain in flight.
        if (c == TOTCH - 1) asm volatile("cp.async.wait_group 0;" ::: "memory");
        else                asm volatile("cp.async.wait_group 1;" ::: "memory");
        __syncthreads();   // single barrier: data visible + prev stage's consumers done

        // issue loads for chunk c+2 into the buffer freed by chunk c-1
        {
            const int nxt = c + NSTAGE - 1;
            if (nxt < TOTCH) load_stage(nxt % NSTAGE, nxt);
        }

        const int s = c % NSTAGE;
        const uint32_t sA = sb + s * STAGE_B;
        const uint32_t sB = sA + ATILE_B;
#pragma unroll
        for (int ks = 0; ks < 4; ks++) {
            uint32_t afr[4][4], bfr[2][4];
            const uint32_t akbs = (ks * 32 + akb) ^ ((arow & 7) << 4);
#pragma unroll
            for (int mt = 0; mt < 4; mt++)
                ldsm4(afr[mt], sA + (arow + mt * 16) * 128 + akbs);
            const uint32_t bkbs = (ks * 32 + bkb) ^ ((brow & 7) << 4);
#pragma unroll
            for (int bt = 0; bt < 2; bt++)
                ldsm4(bfr[bt], sB + (brow + bt * 16) * 128 + bkbs);
#pragma unroll
            for (int mt = 0; mt < 4; mt++)
#pragma unroll
                for (int nt = 0; nt < 4; nt++)
                    mma16816(acc[mt][nt], afr[mt], &bfr[nt >> 1][(nt & 1) * 2]);
        }

        // ---- per-n-tile epilogue (registers + STG only; pipeline stays live) ----
        if ((c & (NCH - 1)) == NCH - 1) {
            const int nt0 = ntBase + (c >> (G1 ? 3 : 5)) * TILE_N;
#pragma unroll
            for (int mt = 0; mt < 4; mt++) {
#pragma unroll
                for (int half = 0; half < 2; half++) {
                    const int rl = wm * 64 + mt * 16 + qrow + half * 8;
                    if (rl >= valid) continue;
                    const size_t rg = (size_t)(off + m0 + rl);
#pragma unroll
                    for (int nt = 0; nt < 4; nt++) {
                        const int colg = nt0 + wn * 32 + nt * 8 + qcol;
                        float v0 = acc[mt][nt][2 * half];
                        float v1 = acc[mt][nt][2 * half + 1];
                        if (G1) {
                            *(__half2*)(g_h + rg * HID + colg) =
                                __floats2half2_rn(fmaxf(v0, 0.f), fmaxf(v1, 0.f));
                        } else {
                            *(__half2*)(g_y + rg * DIM + colg) = __floats2half2_rn(v0, v1);
                        }
                    }
                }
            }
#pragma unroll
            for (int a = 0; a < 4; a++)
#pragma unroll
                for (int b = 0; b < 4; b++)
#pragma unroll
                    for (int q = 0; q < 4; q++) acc[a][b][q] = 0.f;
        }
    }
}

// out[t] = w0 * y[row0] + w1 * y[row1]   (128 threads x 4 floats = 512 floats)
__global__ void combine_kernel(float* __restrict__ out) {
    int t = blockIdx.x;
    int e0 = g_etok[2 * t], e1 = g_etok[2 * t + 1];
    int r0 = g_off[e0] + g_ptok[2 * t];
    int r1 = g_off[e1] + g_ptok[2 * t + 1];
    float w0 = g_wtok[2 * t], w1 = g_wtok[2 * t + 1];
    int i = threadIdx.x;
    uint2 a = ((const uint2*)(g_y + (size_t)r0 * DIM))[i];   // 4 halfs
    uint2 b = ((const uint2*)(g_y + (size_t)r1 * DIM))[i];
    __half2 a0 = *(__half2*)&a.x, a1 = *(__half2*)&a.y;
    __half2 b0 = *(__half2*)&b.x, b1 = *(__half2*)&b.y;
    float4 o;
    o.x = w0 * __low2float(a0)  + w1 * __low2float(b0);
    o.y = w0 * __high2float(a0) + w1 * __high2float(b0);
    o.z = w0 * __low2float(a1)  + w1 * __low2float(b1);
    o.w = w0 * __high2float(a1) + w1 * __high2float(b1);
    ((float4*)(out + (size_t)t * DIM))[i] = o;
}

// ---------------- launch ----------------
extern "C" void kernel_launch(void* const* d_in, const int* in_sizes, int n_in,
                              void* d_out, int out_size) {
    const float* x  = (const float*)d_in[0];
    const float* gw = (const float*)d_in[1];
    const float* w1 = (const float*)d_in[2];
    const float* w2 = (const float*)d_in[3];
    float* out = (float*)d_out;

    cudaFuncSetAttribute(moe_gemm_kernel<true>,
                         cudaFuncAttributeMaxDynamicSharedMemorySize, SMEM_BYTES);
    cudaFuncSetAttribute(moe_gemm_kernel<false>,
                         cudaFuncAttributeMaxDynamicSharedMemorySize, SMEM_BYTES);

    init_kernel<<<1, 32>>>();
    gate_kernel<<<T_TOK / 8, 256>>>(x, gw);
    scan_kernel<<<1, 32>>>();
    cvtw_kernel<<<2048, 256>>>(w1, w2);
    moe_gemm_kernel<true ><<<dim3(MAXMB, HID / TILE_N / NT_ITER, 1), 256, SMEM_BYTES>>>();
    moe_gemm_kernel<false><<<dim3(MAXMB, DIM / TILE_N / NT_ITER, 1), 256, SMEM_BYTES>>>();
    combine_kernel<<<T_TOK, 128>>>(out);
}

// round 8
// speedup vs baseline: 1.0018x; 1.0018x over previous
#include <cuda_runtime.h>
#include <cuda_fp16.h>
#include <cstdint>
#include <cstddef>

// ---------------- problem constants ----------------
#define T_TOK 32768
#define DIM   512
#define HID   2048
#define NEXP  8
#define TOPK  2
#define MAXMB 520                      // max total m-blocks: 512 + 8 (ceil slack)

// ---------------- GEMM tiling ----------------
#define TILE_M   128
#define TILE_N   128
#define CHUNK_K  64                    // fp16 elements per K-chunk = 128 bytes
#define NSTAGE   3
#define NT_ITER  2                     // n-tiles per CTA, pipelined across the boundary
#define ATILE_B  (TILE_M * 128)        // 16 KB
#define STAGE_B  (2 * ATILE_B)         // A + B = 32 KB
#define SMEM_BYTES (NSTAGE * STAGE_B)  // 96 KB -> 2 CTAs/SM

// ---------------- device scratch (allocation-free rule: __device__ globals) ----------------
__device__ __align__(256) __half g_xh [T_TOK * DIM];                 // fp16 tokens
__device__ __align__(256) __half g_w1h[NEXP * HID * DIM];            // fp16 w1
__device__ __align__(256) __half g_w2h[NEXP * DIM * HID];            // fp16 w2
__device__ __align__(256) __half g_h  [(size_t)T_TOK * TOPK * HID];  // gathered hidden (relu'd)
__device__ __align__(256) __half g_y  [(size_t)T_TOK * TOPK * DIM];  // per-row expert output (fp16)
__device__ int   g_cnt[NEXP];
__device__ int   g_off[NEXP];
__device__ int   g_boff[NEXP + 1];            // m-block prefix per expert
__device__ int   g_gather[NEXP * T_TOK];      // expert -> token list
__device__ int   g_etok[T_TOK * TOPK];        // token -> expert ids
__device__ int   g_ptok[T_TOK * TOPK];        // token -> position within expert list
__device__ float g_wtok[T_TOK * TOPK];        // token -> softmax weights

// ---------------- PTX helpers (all baseline sm_80+ instructions) ----------------
__device__ __forceinline__ uint32_t smem_u32(const void* p) {
    uint32_t a;
    asm("{ .reg .u64 t; cvta.to.shared.u64 t, %1; cvt.u32.u64 %0, t; }" : "=r"(a) : "l"(p));
    return a;
}

__device__ __forceinline__ void cpa16(uint32_t dst, const void* src, unsigned srcsz) {
    asm volatile("cp.async.cg.shared.global [%0], [%1], 16, %2;"
                 :: "r"(dst), "l"(src), "r"(srcsz) : "memory");
}

__device__ __forceinline__ void ldsm4(uint32_t* r, uint32_t addr) {
    asm volatile("ldmatrix.sync.aligned.m8n8.x4.shared.b16 {%0,%1,%2,%3}, [%4];"
                 : "=r"(r[0]), "=r"(r[1]), "=r"(r[2]), "=r"(r[3]) : "r"(addr));
}

__device__ __forceinline__ void mma16816(float* c, const uint32_t* a, const uint32_t* b) {
    asm volatile("mma.sync.aligned.m16n8k16.row.col.f32.f16.f16.f32 "
                 "{%0,%1,%2,%3}, {%4,%5,%6,%7}, {%8,%9}, {%0,%1,%2,%3};"
                 : "+f"(c[0]), "+f"(c[1]), "+f"(c[2]), "+f"(c[3])
                 : "r"(a[0]), "r"(a[1]), "r"(a[2]), "r"(a[3]), "r"(b[0]), "r"(b[1]));
}

__device__ __forceinline__ uint32_t h2u(__half2 h) {
    uint32_t u;
    *(__half2*)&u = h;
    return u;
}

// ---------------- tiny kernels ----------------
__global__ void init_kernel() {
    if (threadIdx.x < NEXP) g_cnt[threadIdx.x] = 0;
}

__global__ void scan_kernel() {
    if (threadIdx.x == 0) {
        int a = 0, b = 0;
        for (int e = 0; e < NEXP; e++) {
            g_off[e] = a;  g_boff[e] = b;
            a += g_cnt[e]; b += (g_cnt[e] + TILE_M - 1) / TILE_M;
        }
        g_boff[NEXP] = b;
    }
}

__global__ void cvtw_kernel(const float* __restrict__ w1, const float* __restrict__ w2) {
    size_t n = (size_t)NEXP * HID * DIM / 4;
    const float4* w1v = (const float4*)w1;
    const float4* w2v = (const float4*)w2;
    for (size_t i = (size_t)blockIdx.x * blockDim.x + threadIdx.x; i < n;
         i += (size_t)gridDim.x * blockDim.x) {
        float4 a = w1v[i], b = w2v[i];
        ((uint2*)g_w1h)[i] = make_uint2(h2u(__floats2half2_rn(a.x, a.y)),
                                        h2u(__floats2half2_rn(a.z, a.w)));
        ((uint2*)g_w2h)[i] = make_uint2(h2u(__floats2half2_rn(b.x, b.y)),
                                        h2u(__floats2half2_rn(b.z, b.w)));
    }
}

// gate: fp32 logits, top-2, softmax. Also emits fp16 x. 8 warps = 8 tokens per block.
__global__ void gate_kernel(const float* __restrict__ x, const float* __restrict__ gw) {
    __shared__ float s_gw[NEXP * DIM];
    for (int i = threadIdx.x; i < NEXP * DIM; i += blockDim.x) s_gw[i] = gw[i];
    __syncthreads();
    int w = threadIdx.x >> 5, lane = threadIdx.x & 31;
    int t = blockIdx.x * 8 + w;
    const float* xr = x + (size_t)t * DIM;
    float xv[16];
#pragma unroll
    for (int i = 0; i < 16; i++) xv[i] = xr[lane + 32 * i];
#pragma unroll
    for (int i = 0; i < 16; i++)
        g_xh[(size_t)t * DIM + lane + 32 * i] = __float2half_rn(xv[i]);
    float acc[NEXP];
#pragma unroll
    for (int e = 0; e < NEXP; e++) {
        float a = 0.f;
#pragma unroll
        for (int i = 0; i < 16; i++) a += xv[i] * s_gw[e * DIM + lane + 32 * i];
        acc[e] = a;
    }
#pragma unroll
    for (int off = 16; off > 0; off >>= 1)
#pragma unroll
        for (int e = 0; e < NEXP; e++) acc[e] += __shfl_xor_sync(0xffffffffu, acc[e], off);
    if (lane == 0) {
        int e0 = 0; float l0 = acc[0];
#pragma unroll
        for (int e = 1; e < NEXP; e++) if (acc[e] > l0) { l0 = acc[e]; e0 = e; }
        int e1 = -1; float l1 = -3.4e38f;
#pragma unroll
        for (int e = 0; e < NEXP; e++) if (e != e0 && acc[e] > l1) { l1 = acc[e]; e1 = e; }
        float p1 = expf(l1 - l0);
        float inv = 1.f / (1.f + p1);
        float w0 = inv, w1v = p1 * inv;
        int pos0 = atomicAdd(&g_cnt[e0], 1);
        int pos1 = atomicAdd(&g_cnt[e1], 1);
        g_gather[e0 * T_TOK + pos0] = t;
        g_gather[e1 * T_TOK + pos1] = t;
        g_etok[2 * t] = e0;  g_etok[2 * t + 1] = e1;
        g_ptok[2 * t] = pos0; g_ptok[2 * t + 1] = pos1;
        g_wtok[2 * t] = w0;  g_wtok[2 * t + 1] = w1v;
    }
}

// ---------------- grouped GEMM via mma.sync (HMMA path; tcgen05 rejected by
// compute_100 PTX target the harness uses) ----------------
// G1: h[rows, HID-tile] = relu( gathered_x[rows, DIM] @ w1[e]^T ), fp16 out
// G2: y[rows, DIM-tile] =        h[rows, HID]        @ w2[e]^T  , fp16 out
// CTA tile 128x128xK, 256 threads, warp grid 2(M) x 4(N), warp tile 64x32.
// Each CTA processes NT_ITER consecutive n-tiles with ONE continuous cp.async
// pipeline: loads for tile j+1 are already in flight while tile j's epilogue
// (registers + STG only) runs, so the pipe never drains at tile boundaries.
template <bool G1>
__global__ void __launch_bounds__(256, 2) moe_gemm_kernel() {
    constexpr int KTOT  = G1 ? DIM : HID;
    constexpr int NCH   = KTOT / CHUNK_K;       // 8 or 32 (power of two)
    constexpr int TOTCH = NT_ITER * NCH;
    const int mb = blockIdx.x;
    if (mb >= g_boff[NEXP]) return;
    int e = 0;
#pragma unroll
    for (int k = 1; k < NEXP; k++) if (mb >= g_boff[k]) e = k;
    const int m0     = (mb - g_boff[e]) * TILE_M;
    const int cnt    = g_cnt[e];
    const int off    = g_off[e];
    const int ntBase = blockIdx.y * NT_ITER * TILE_N;

    extern __shared__ char smem[];
    const uint32_t sb = smem_u32(smem);
    const int tid = threadIdx.x, wid = tid >> 5, lane = tid & 31;
    const int wm = wid & 1, wn = wid >> 1;              // warp coords: 2(M) x 4(N)

    const int valid = min(cnt - m0, TILE_M);

    // ---- load mapping: thread t -> row t/2, four 16B segments ----
    const int lr = tid >> 1;                            // 0..127
    const int sseg = (tid & 1) * 4;                     // 0 or 4
    const unsigned asz = (lr < valid) ? 16u : 0u;       // zero-fill invalid rows
    const int ar = min(lr, valid - 1);
    const char* aBase;
    if (G1) {
        int tok = g_gather[e * T_TOK + m0 + ar];
        aBase = (const char*)(g_xh + (size_t)tok * DIM);
    } else {
        aBase = (const char*)(g_h + (size_t)(off + m0 + ar) * HID);
    }
    // B base for the first n-tile of this CTA; +TILE_STRIDE_B bytes per n-tile.
    const char* bBase0 = G1
        ? (const char*)(g_w1h + ((size_t)e * HID + ntBase + lr) * DIM)
        : (const char*)(g_w2h + ((size_t)e * DIM + ntBase + lr) * HID);
    constexpr size_t TILE_STRIDE_B = (size_t)TILE_N * KTOT * 2;
    const int rowoff = lr * 128;
    const int swr = (lr & 7);

    // c = global chunk index: n-tile = c / NCH, k-chunk = c % NCH
    auto load_stage = [&](int stg, int c) {
        const int ch = c & (NCH - 1);
        const char* bp = bBase0 + (size_t)(c >> (G1 ? 3 : 5)) * TILE_STRIDE_B + ch * 128;
        const char* ap = aBase + ch * 128;
        uint32_t s0 = sb + stg * STAGE_B;
#pragma unroll
        for (int i = 0; i < 4; i++) {
            int s = sseg + i;
            uint32_t sw = rowoff + (((unsigned)(s ^ swr)) << 4);
            cpa16(s0 + sw,            ap + s * 16, asz);
            cpa16(s0 + ATILE_B + sw,  bp + s * 16, 16u);
        }
        asm volatile("cp.async.commit_group;" ::: "memory");
    };

#pragma unroll
    for (int i = 0; i < NSTAGE - 1; i++) load_stage(i, i);

    float acc[4][4][4];
#pragma unroll
    for (int a = 0; a < 4; a++)
#pragma unroll
        for (int b = 0; b < 4; b++)
#pragma unroll
            for (int c = 0; c < 4; c++) acc[a][b][c] = 0.f;

    // ldmatrix lane addressing
    const int arow = wm * 64 + (lane & 15);             // A row within tile
    const int akb  = (lane & 16);                       // +16B for k8..15 halves
    const int brow = wn * 32 + (lane & 7) + ((lane & 16) >> 1);
    const int bkb  = ((lane & 8) << 1);

    const int qrow = lane >> 2, qcol = (lane & 3) * 2;

    for (int c = 0; c < TOTCH; c++) {
        // stage c must be complete; stage c+1 may remain in flight.
        if (c == TOTCH - 1) asm volatile("cp.async.wait_group 0;" ::: "memory");
        else                asm volatile("cp.async.wait_group 1;" ::: "memory");
        __syncthreads();   // single barrier: data visible + prev stage's consumers done

        // issue loads for chunk c+2 into the buffer freed by chunk c-1
        {
            const int nxt = c + NSTAGE - 1;
            if (nxt < TOTCH) load_stage(nxt % NSTAGE, nxt);
        }

        const int s = c % NSTAGE;
        const uint32_t sA = sb + s * STAGE_B;
        const uint32_t sB = sA + ATILE_B;
#pragma unroll
        for (int ks = 0; ks < 4; ks++) {
            uint32_t afr[4][4], bfr[2][4];
            const uint32_t akbs = (ks * 32 + akb) ^ ((arow & 7) << 4);
#pragma unroll
            for (int mt = 0; mt < 4; mt++)
                ldsm4(afr[mt], sA + (arow + mt * 16) * 128 + akbs);
            const uint32_t bkbs = (ks * 32 + bkb) ^ ((brow & 7) << 4);
#pragma unroll
            for (int bt = 0; bt < 2; bt++)
                ldsm4(bfr[bt], sB + (brow + bt * 16) * 128 + bkbs);
#pragma unroll
            for (int mt = 0; mt < 4; mt++)
#pragma unroll
                for (int nt = 0; nt < 4; nt++)
                    mma16816(acc[mt][nt], afr[mt], &bfr[nt >> 1][(nt & 1) * 2]);
        }

        // ---- per-n-tile epilogue (registers + STG only; pipeline stays live) ----
        if ((c & (NCH - 1)) == NCH - 1) {
            const int nt0 = ntBase + (c >> (G1 ? 3 : 5)) * TILE_N;
#pragma unroll
            for (int mt = 0; mt < 4; mt++) {
#pragma unroll
                for (int half = 0; half < 2; half++) {
                    const int rl = wm * 64 + mt * 16 + qrow + half * 8;
                    if (rl >= valid) continue;
                    const size_t rg = (size_t)(off + m0 + rl);
#pragma unroll
                    for (int nt = 0; nt < 4; nt++) {
                        const int colg = nt0 + wn * 32 + nt * 8 + qcol;
                        float v0 = acc[mt][nt][2 * half];
                        float v1 = acc[mt][nt][2 * half + 1];
                        if (G1) {
                            *(__half2*)(g_h + rg * HID + colg) =
                                __floats2half2_rn(fmaxf(v0, 0.f), fmaxf(v1, 0.f));
                        } else {
                            *(__half2*)(g_y + rg * DIM + colg) = __floats2half2_rn(v0, v1);
                        }
                    }
                }
            }
#pragma unroll
            for (int a = 0; a < 4; a++)
#pragma unroll
                for (int b = 0; b < 4; b++)
#pragma unroll
                    for (int q = 0; q < 4; q++) acc[a][b][q] = 0.f;
        }
    }
}

// out[t] = w0 * y[row0] + w1 * y[row1]   (128 threads x 4 floats = 512 floats)
__global__ void combine_kernel(float* __restrict__ out) {
    int t = blockIdx.x;
    int e0 = g_etok[2 * t], e1 = g_etok[2 * t + 1];
    int r0 = g_off[e0] + g_ptok[2 * t];
    int r1 = g_off[e1] + g_ptok[2 * t + 1];
    float w0 = g_wtok[2 * t], w1 = g_wtok[2 * t + 1];
    int i = threadIdx.x;
    uint2 a = ((const uint2*)(g_y + (size_t)r0 * DIM))[i];   // 4 halfs
    uint2 b = ((const uint2*)(g_y + (size_t)r1 * DIM))[i];
    __half2 a0 = *(__half2*)&a.x, a1 = *(__half2*)&a.y;
    __half2 b0 = *(__half2*)&b.x, b1 = *(__half2*)&b.y;
    float4 o;
    o.x = w0 * __low2float(a0)  + w1 * __low2float(b0);
    o.y = w0 * __high2float(a0) + w1 * __high2float(b0);
    o.z = w0 * __low2float(a1)  + w1 * __low2float(b1);
    o.w = w0 * __high2float(a1) + w1 * __high2float(b1);
    ((float4*)(out + (size_t)t * DIM))[i] = o;
}

// ---------------- launch ----------------
extern "C" void kernel_launch(void* const* d_in, const int* in_sizes, int n_in,
                              void* d_out, int out_size) {
    const float* x  = (const float*)d_in[0];
    const float* gw = (const float*)d_in[1];
    const float* w1 = (const float*)d_in[2];
    const float* w2 = (const float*)d_in[3];
    float* out = (float*)d_out;

    cudaFuncSetAttribute(moe_gemm_kernel<true>,
                         cudaFuncAttributeMaxDynamicSharedMemorySize, SMEM_BYTES);
    cudaFuncSetAttribute(moe_gemm_kernel<false>,
                         cudaFuncAttributeMaxDynamicSharedMemorySize, SMEM_BYTES);

    init_kernel<<<1, 32>>>();
    gate_kernel<<<T_TOK / 8, 256>>>(x, gw);
    scan_kernel<<<1, 32>>>();
    cvtw_kernel<<<2048, 256>>>(w1, w2);
    moe_gemm_kernel<true ><<<dim3(MAXMB, HID / TILE_N / NT_ITER, 1), 256, SMEM_BYTES>>>();
    moe_gemm_kernel<false><<<dim3(MAXMB, DIM / TILE_N / NT_ITER, 1), 256, SMEM_BYTES>>>();
    combine_kernel<<<T_TOK, 128>>>(out);
}

// round 9
// speedup vs baseline: 1.0228x; 1.0210x over previous
#include <cuda_runtime.h>
#include <cuda_fp16.h>
#include <cstdint>
#include <cstddef>

// ---------------- problem constants ----------------
#define T_TOK 32768
#define DIM   512
#define HID   2048
#define NEXP  8
#define TOPK  2
#define MAXMB 520                      // max total m-blocks: 512 + 8 (ceil slack)

// ---------------- GEMM tiling ----------------
#define TILE_M   128
#define TILE_N   128
#define CHUNK_K  64                    // fp16 elements per K-chunk = 128 bytes
#define NSTAGE   3
#define ATILE_B  (TILE_M * 128)        // 16 KB
#define STAGE_B  (2 * ATILE_B)         // A + B = 32 KB
#define SMEM_BYTES (NSTAGE * STAGE_B)  // 96 KB -> 2 CTAs/SM

// ---------------- device scratch (allocation-free rule: __device__ globals) ----------------
__device__ __align__(256) __half g_xh [T_TOK * DIM];                 // fp16 tokens
__device__ __align__(256) __half g_w1h[NEXP * HID * DIM];            // fp16 w1
__device__ __align__(256) __half g_w2h[NEXP * DIM * HID];            // fp16 w2
__device__ __align__(256) __half g_h  [(size_t)T_TOK * TOPK * HID];  // gathered hidden (relu'd)
__device__ int   g_cnt[NEXP];
__device__ int   g_off[NEXP];
__device__ int   g_boff[NEXP + 1];            // m-block prefix per expert
__device__ int   g_gather[NEXP * T_TOK];      // expert -> token list
__device__ float g_wslot[NEXP * T_TOK];       // expert slot -> softmax weight

// ---------------- PTX helpers (all baseline sm_80+ instructions) ----------------
__device__ __forceinline__ uint32_t smem_u32(const void* p) {
    uint32_t a;
    asm("{ .reg .u64 t; cvta.to.shared.u64 t, %1; cvt.u32.u64 %0, t; }" : "=r"(a) : "l"(p));
    return a;
}

__device__ __forceinline__ void cpa16(uint32_t dst, const void* src, unsigned srcsz) {
    asm volatile("cp.async.cg.shared.global [%0], [%1], 16, %2;"
                 :: "r"(dst), "l"(src), "r"(srcsz) : "memory");
}

__device__ __forceinline__ void ldsm4(uint32_t* r, uint32_t addr) {
    asm volatile("ldmatrix.sync.aligned.m8n8.x4.shared.b16 {%0,%1,%2,%3}, [%4];"
                 : "=r"(r[0]), "=r"(r[1]), "=r"(r[2]), "=r"(r[3]) : "r"(addr));
}

__device__ __forceinline__ void mma16816(float* c, const uint32_t* a, const uint32_t* b) {
    asm volatile("mma.sync.aligned.m16n8k16.row.col.f32.f16.f16.f32 "
                 "{%0,%1,%2,%3}, {%4,%5,%6,%7}, {%8,%9}, {%0,%1,%2,%3};"
                 : "+f"(c[0]), "+f"(c[1]), "+f"(c[2]), "+f"(c[3])
                 : "r"(a[0]), "r"(a[1]), "r"(a[2]), "r"(a[3]), "r"(b[0]), "r"(b[1]));
}

__device__ __forceinline__ uint32_t h2u(__half2 h) {
    uint32_t u;
    *(__half2*)&u = h;
    return u;
}

// ---------------- tiny kernels ----------------
__global__ void init_kernel() {
    if (threadIdx.x < NEXP) g_cnt[threadIdx.x] = 0;
}

__global__ void scan_kernel() {
    if (threadIdx.x == 0) {
        int a = 0, b = 0;
        for (int e = 0; e < NEXP; e++) {
            g_off[e] = a;  g_boff[e] = b;
            a += g_cnt[e]; b += (g_cnt[e] + TILE_M - 1) / TILE_M;
        }
        g_boff[NEXP] = b;
    }
}

__global__ void cvtw_kernel(const float* __restrict__ w1, const float* __restrict__ w2) {
    size_t n = (size_t)NEXP * HID * DIM / 4;
    const float4* w1v = (const float4*)w1;
    const float4* w2v = (const float4*)w2;
    for (size_t i = (size_t)blockIdx.x * blockDim.x + threadIdx.x; i < n;
         i += (size_t)gridDim.x * blockDim.x) {
        float4 a = w1v[i], b = w2v[i];
        ((uint2*)g_w1h)[i] = make_uint2(h2u(__floats2half2_rn(a.x, a.y)),
                                        h2u(__floats2half2_rn(a.z, a.w)));
        ((uint2*)g_w2h)[i] = make_uint2(h2u(__floats2half2_rn(b.x, b.y)),
                                        h2u(__floats2half2_rn(b.z, b.w)));
    }
}

// gate: fp32 logits, top-2, softmax. Also emits fp16 x AND zeroes `out`
// (out is the atomic accumulation target of GEMM2). 8 warps = 8 tokens / block.
__global__ void gate_kernel(const float* __restrict__ x, const float* __restrict__ gw,
                            float* __restrict__ out) {
    __shared__ float s_gw[NEXP * DIM];
    for (int i = threadIdx.x; i < NEXP * DIM; i += blockDim.x) s_gw[i] = gw[i];
    __syncthreads();
    int w = threadIdx.x >> 5, lane = threadIdx.x & 31;
    int t = blockIdx.x * 8 + w;
    // zero this token's output row (128B-coalesced float4 stores per warp)
    {
        float4* orow = (float4*)(out + (size_t)t * DIM);
#pragma unroll
        for (int i = 0; i < 4; i++)
            orow[lane + 32 * i] = make_float4(0.f, 0.f, 0.f, 0.f);
    }
    const float* xr = x + (size_t)t * DIM;
    float xv[16];
#pragma unroll
    for (int i = 0; i < 16; i++) xv[i] = xr[lane + 32 * i];
#pragma unroll
    for (int i = 0; i < 16; i++)
        g_xh[(size_t)t * DIM + lane + 32 * i] = __float2half_rn(xv[i]);
    float acc[NEXP];
#pragma unroll
    for (int e = 0; e < NEXP; e++) {
        float a = 0.f;
#pragma unroll
        for (int i = 0; i < 16; i++) a += xv[i] * s_gw[e * DIM + lane + 32 * i];
        acc[e] = a;
    }
#pragma unroll
    for (int off = 16; off > 0; off >>= 1)
#pragma unroll
        for (int e = 0; e < NEXP; e++) acc[e] += __shfl_xor_sync(0xffffffffu, acc[e], off);
    if (lane == 0) {
        int e0 = 0; float l0 = acc[0];
#pragma unroll
        for (int e = 1; e < NEXP; e++) if (acc[e] > l0) { l0 = acc[e]; e0 = e; }
        int e1 = -1; float l1 = -3.4e38f;
#pragma unroll
        for (int e = 0; e < NEXP; e++) if (e != e0 && acc[e] > l1) { l1 = acc[e]; e1 = e; }
        float p1 = expf(l1 - l0);
        float inv = 1.f / (1.f + p1);
        float w0 = inv, w1v = p1 * inv;
        int pos0 = atomicAdd(&g_cnt[e0], 1);
        int pos1 = atomicAdd(&g_cnt[e1], 1);
        g_gather[e0 * T_TOK + pos0] = t;
        g_gather[e1 * T_TOK + pos1] = t;
        g_wslot[e0 * T_TOK + pos0] = w0;
        g_wslot[e1 * T_TOK + pos1] = w1v;
    }
}

// ---------------- grouped GEMM via mma.sync (HMMA path; tcgen05 rejected by
// compute_100 PTX target the harness uses) ----------------
// G1: h[rows, HID-tile] = relu( gathered_x[rows, DIM] @ w1[e]^T ), fp16 out
// G2: out[tok] += w_slot * ( h[rows, HID] @ w2[e]^T )   via atomicAdd (exactly
//     two fp32 contributions per element onto a zeroed base -> commutative,
//     deterministic across replays)
// CTA tile 128x128xK, 256 threads, warp grid 2(M) x 4(N), warp tile 64x32.
// 3 stages x 32KB = 96KB smem -> 2 CTAs/SM (16 warps), single sync per chunk.
template <bool G1>
__global__ void __launch_bounds__(256, 2) moe_gemm_kernel(float* __restrict__ out) {
    constexpr int KTOT = G1 ? DIM : HID;
    constexpr int NCH  = KTOT / CHUNK_K;   // 8 or 32
    const int mb = blockIdx.x;
    if (mb >= g_boff[NEXP]) return;
    int e = 0;
#pragma unroll
    for (int k = 1; k < NEXP; k++) if (mb >= g_boff[k]) e = k;
    const int m0  = (mb - g_boff[e]) * TILE_M;
    const int cnt = g_cnt[e];
    const int off = g_off[e];
    const int nt0 = blockIdx.y * TILE_N;

    extern __shared__ char smem[];
    const uint32_t sb = smem_u32(smem);
    const int tid = threadIdx.x, wid = tid >> 5, lane = tid & 31;
    const int wm = wid & 1, wn = wid >> 1;              // warp coords: 2(M) x 4(N)

    const int valid = min(cnt - m0, TILE_M);

    // ---- load mapping: thread t -> row t/2, four 16B segments ----
    const int lr = tid >> 1;                            // 0..127
    const int sseg = (tid & 1) * 4;                     // 0 or 4
    const unsigned asz = (lr < valid) ? 16u : 0u;       // zero-fill invalid rows
    const int ar = min(lr, valid - 1);
    const char* aBase;
    if (G1) {
        int tok = g_gather[e * T_TOK + m0 + ar];
        aBase = (const char*)(g_xh + (size_t)tok * DIM);
    } else {
        aBase = (const char*)(g_h + (size_t)(off + m0 + ar) * HID);
    }
    const char* bBase = G1
        ? (const char*)(g_w1h + ((size_t)e * HID + nt0 + lr) * DIM)
        : (const char*)(g_w2h + ((size_t)e * DIM + nt0 + lr) * HID);
    const int rowoff = lr * 128;
    const int swr = (lr & 7);

    auto load_stage = [&](int stg, int ch) {
        uint32_t s0 = sb + stg * STAGE_B;
#pragma unroll
        for (int i = 0; i < 4; i++) {
            int s = sseg + i;
            uint32_t sw = rowoff + (((unsigned)(s ^ swr)) << 4);
            cpa16(s0 + sw,            aBase + ch * 128 + s * 16, asz);
            cpa16(s0 + ATILE_B + sw,  bBase + ch * 128 + s * 16, 16u);
        }
        asm volatile("cp.async.commit_group;" ::: "memory");
    };

#pragma unroll
    for (int i = 0; i < NSTAGE - 1; i++) load_stage(i, i);

    float acc[4][4][4];
#pragma unroll
    for (int a = 0; a < 4; a++)
#pragma unroll
        for (int b = 0; b < 4; b++)
#pragma unroll
            for (int c = 0; c < 4; c++) acc[a][b][c] = 0.f;

    // ldmatrix lane addressing
    const int arow = wm * 64 + (lane & 15);             // A row within tile
    const int akb  = (lane & 16);                       // +16B for k8..15 halves
    const int brow = wn * 32 + (lane & 7) + ((lane & 16) >> 1);
    const int bkb  = ((lane & 8) << 1);

    for (int i = 0; i < NCH; i++) {
        // stage i must be complete; stage i+1 may remain in flight.
        if (i == NCH - 1) asm volatile("cp.async.wait_group 0;" ::: "memory");
        else              asm volatile("cp.async.wait_group 1;" ::: "memory");
        __syncthreads();   // single barrier: data visible + prev stage's consumers done

        // issue loads for stage i+2 into the buffer freed by stage i-1
        {
            const int nxt = i + NSTAGE - 1;
            if (nxt < NCH) load_stage(nxt % NSTAGE, nxt);
        }

        const int s = i % NSTAGE;
        const uint32_t sA = sb + s * STAGE_B;
        const uint32_t sB = sA + ATILE_B;
#pragma unroll
        for (int ks = 0; ks < 4; ks++) {
            uint32_t afr[4][4], bfr[2][4];
            const uint32_t akbs = (ks * 32 + akb) ^ ((arow & 7) << 4);
#pragma unroll
            for (int mt = 0; mt < 4; mt++)
                ldsm4(afr[mt], sA + (arow + mt * 16) * 128 + akbs);
            const uint32_t bkbs = (ks * 32 + bkb) ^ ((brow & 7) << 4);
#pragma unroll
            for (int bt = 0; bt < 2; bt++)
                ldsm4(bfr[bt], sB + (brow + bt * 16) * 128 + bkbs);
#pragma unroll
            for (int mt = 0; mt < 4; mt++)
#pragma unroll
                for (int nt = 0; nt < 4; nt++)
                    mma16816(acc[mt][nt], afr[mt], &bfr[nt >> 1][(nt & 1) * 2]);
        }
    }

    // ---- epilogue ----
    const int qrow = lane >> 2, qcol = (lane & 3) * 2;
#pragma unroll
    for (int mt = 0; mt < 4; mt++) {
#pragma unroll
        for (int half = 0; half < 2; half++) {
            const int rl = wm * 64 + mt * 16 + qrow + half * 8;
            if (rl >= valid) continue;
            if (G1) {
                const size_t rg = (size_t)(off + m0 + rl);
#pragma unroll
                for (int nt = 0; nt < 4; nt++) {
                    const int colg = nt0 + wn * 32 + nt * 8 + qcol;
                    *(__half2*)(g_h + rg * HID + colg) =
                        __floats2half2_rn(fmaxf(acc[mt][nt][2 * half], 0.f),
                                          fmaxf(acc[mt][nt][2 * half + 1], 0.f));
                }
            } else {
                const int slot = e * T_TOK + m0 + rl;
                const int tok  = g_gather[slot];
                const float w  = g_wslot[slot];
                float* orow = out + (size_t)tok * DIM;
#pragma unroll
                for (int nt = 0; nt < 4; nt++) {
                    const int colg = nt0 + wn * 32 + nt * 8 + qcol;
                    atomicAdd(orow + colg,     w * acc[mt][nt][2 * half]);
                    atomicAdd(orow + colg + 1, w * acc[mt][nt][2 * half + 1]);
                }
            }
        }
    }
}

// ---------------- launch ----------------
extern "C" void kernel_launch(void* const* d_in, const int* in_sizes, int n_in,
                              void* d_out, int out_size) {
    const float* x  = (const float*)d_in[0];
    const float* gw = (const float*)d_in[1];
    const float* w1 = (const float*)d_in[2];
    const float* w2 = (const float*)d_in[3];
    float* out = (float*)d_out;

    cudaFuncSetAttribute(moe_gemm_kernel<true>,
                         cudaFuncAttributeMaxDynamicSharedMemorySize, SMEM_BYTES);
    cudaFuncSetAttribute(moe_gemm_kernel<false>,
                         cudaFuncAttributeMaxDynamicSharedMemorySize, SMEM_BYTES);

    init_kernel<<<1, 32>>>();
    gate_kernel<<<T_TOK / 8, 256>>>(x, gw, out);
    scan_kernel<<<1, 32>>>();
    cvtw_kernel<<<2048, 256>>>(w1, w2);
    moe_gemm_kernel<true ><<<dim3(MAXMB, HID / TILE_N, 1), 256, SMEM_BYTES>>>(out);
    moe_gemm_kernel<false><<<dim3(MAXMB, DIM / TILE_N, 1), 256, SMEM_BYTES>>>(out);
}

// round 10
// speedup vs baseline: 1.0349x; 1.0118x over previous
#include <cuda_runtime.h>
#include <cuda_fp16.h>
#include <cstdint>
#include <cstddef>

// ---------------- problem constants ----------------
#define T_TOK 32768
#define DIM   512
#define HID   2048
#define NEXP  8
#define TOPK  2
#define MAXMB 520                      // max total m-blocks: 512 + 8 (ceil slack)

// ---------------- GEMM tiling ----------------
#define TILE_M   128
#define TILE_N   128
#define CHUNK_K  64                    // fp16 elements per K-chunk = 128 bytes
#define NSTAGE   3
#define ATILE_B  (TILE_M * 128)        // 16 KB
#define STAGE_B  (2 * ATILE_B)         // A + B = 32 KB
#define SMEM_BYTES (NSTAGE * STAGE_B)  // 96 KB -> 2 CTAs/SM

// prep kernel grid split
#define GATE_BLOCKS (T_TOK / 8)        // 4096
#define CVT_BLOCKS  2048
#define PREP_BLOCKS (GATE_BLOCKS + CVT_BLOCKS)

// ---------------- device scratch (allocation-free rule: __device__ globals) ----------------
__device__ __align__(256) __half g_xh [T_TOK * DIM];                 // fp16 tokens
__device__ __align__(256) __half g_w1h[NEXP * HID * DIM];            // fp16 w1
__device__ __align__(256) __half g_w2h[NEXP * DIM * HID];            // fp16 w2
__device__ __align__(256) __half g_h  [(size_t)T_TOK * TOPK * HID];  // gathered hidden (relu'd)
__device__ __align__(256) __half g_y  [(size_t)T_TOK * TOPK * DIM];  // per-row expert output (fp16)
__device__ int   g_cnt[NEXP];
__device__ int   g_off[NEXP];
__device__ int   g_boff[NEXP + 1];            // m-block prefix per expert
__device__ int   g_gather[NEXP * T_TOK];      // expert -> token list
__device__ int   g_etok[T_TOK * TOPK];        // token -> expert ids
__device__ int   g_ptok[T_TOK * TOPK];        // token -> position within expert list
__device__ float g_wtok[T_TOK * TOPK];        // token -> softmax weights

// ---------------- PTX helpers (all baseline sm_80+ instructions) ----------------
__device__ __forceinline__ uint32_t smem_u32(const void* p) {
    uint32_t a;
    asm("{ .reg .u64 t; cvta.to.shared.u64 t, %1; cvt.u32.u64 %0, t; }" : "=r"(a) : "l"(p));
    return a;
}

__device__ __forceinline__ void cpa16(uint32_t dst, const void* src, unsigned srcsz) {
    asm volatile("cp.async.cg.shared.global [%0], [%1], 16, %2;"
                 :: "r"(dst), "l"(src), "r"(srcsz) : "memory");
}

__device__ __forceinline__ void ldsm4(uint32_t* r, uint32_t addr) {
    asm volatile("ldmatrix.sync.aligned.m8n8.x4.shared.b16 {%0,%1,%2,%3}, [%4];"
                 : "=r"(r[0]), "=r"(r[1]), "=r"(r[2]), "=r"(r[3]) : "r"(addr));
}

__device__ __forceinline__ void mma16816(float* c, const uint32_t* a, const uint32_t* b) {
    asm volatile("mma.sync.aligned.m16n8k16.row.col.f32.f16.f16.f32 "
                 "{%0,%1,%2,%3}, {%4,%5,%6,%7}, {%8,%9}, {%0,%1,%2,%3};"
                 : "+f"(c[0]), "+f"(c[1]), "+f"(c[2]), "+f"(c[3])
                 : "r"(a[0]), "r"(a[1]), "r"(a[2]), "r"(a[3]), "r"(b[0]), "r"(b[1]));
}

__device__ __forceinline__ uint32_t h2u(__half2 h) {
    uint32_t u;
    *(__half2*)&u = h;
    return u;
}

// ---------------- tiny kernels ----------------
__global__ void init_kernel() {
    if (threadIdx.x < NEXP) g_cnt[threadIdx.x] = 0;
}

__global__ void scan_kernel() {
    if (threadIdx.x == 0) {
        int a = 0, b = 0;
        for (int e = 0; e < NEXP; e++) {
            g_off[e] = a;  g_boff[e] = b;
            a += g_cnt[e]; b += (g_cnt[e] + TILE_M - 1) / TILE_M;
        }
        g_boff[NEXP] = b;
    }
}

// ---------------- fused prep kernel: gate (blocks [0,4096)) + weight convert
// (blocks [4096,6144)). The two workloads are independent; interleaving them
// in one wave lets the DRAM-streaming convert blocks fill the gate blocks'
// latency shadows. ----------------
__global__ void prep_kernel(const float* __restrict__ x, const float* __restrict__ gw,
                            const float* __restrict__ w1, const float* __restrict__ w2) {
    if (blockIdx.x >= GATE_BLOCKS) {
        // ---- weight conversion part ----
        size_t n = (size_t)NEXP * HID * DIM / 4;
        const float4* w1v = (const float4*)w1;
        const float4* w2v = (const float4*)w2;
        for (size_t i = (size_t)(blockIdx.x - GATE_BLOCKS) * blockDim.x + threadIdx.x;
             i < n; i += (size_t)CVT_BLOCKS * blockDim.x) {
            float4 a = w1v[i], b = w2v[i];
            ((uint2*)g_w1h)[i] = make_uint2(h2u(__floats2half2_rn(a.x, a.y)),
                                            h2u(__floats2half2_rn(a.z, a.w)));
            ((uint2*)g_w2h)[i] = make_uint2(h2u(__floats2half2_rn(b.x, b.y)),
                                            h2u(__floats2half2_rn(b.z, b.w)));
        }
        return;
    }
    // ---- gate part: fp32 logits, top-2, softmax; emits fp16 x. 8 tokens/block ----
    __shared__ float s_gw[NEXP * DIM];
    for (int i = threadIdx.x; i < NEXP * DIM; i += blockDim.x) s_gw[i] = gw[i];
    __syncthreads();
    int w = threadIdx.x >> 5, lane = threadIdx.x & 31;
    int t = blockIdx.x * 8 + w;
    const float* xr = x + (size_t)t * DIM;
    float xv[16];
#pragma unroll
    for (int i = 0; i < 16; i++) xv[i] = xr[lane + 32 * i];
#pragma unroll
    for (int i = 0; i < 16; i++)
        g_xh[(size_t)t * DIM + lane + 32 * i] = __float2half_rn(xv[i]);
    float acc[NEXP];
#pragma unroll
    for (int e = 0; e < NEXP; e++) {
        float a = 0.f;
#pragma unroll
        for (int i = 0; i < 16; i++) a += xv[i] * s_gw[e * DIM + lane + 32 * i];
        acc[e] = a;
    }
#pragma unroll
    for (int off = 16; off > 0; off >>= 1)
#pragma unroll
        for (int e = 0; e < NEXP; e++) acc[e] += __shfl_xor_sync(0xffffffffu, acc[e], off);
    if (lane == 0) {
        int e0 = 0; float l0 = acc[0];
#pragma unroll
        for (int e = 1; e < NEXP; e++) if (acc[e] > l0) { l0 = acc[e]; e0 = e; }
        int e1 = -1; float l1 = -3.4e38f;
#pragma unroll
        for (int e = 0; e < NEXP; e++) if (e != e0 && acc[e] > l1) { l1 = acc[e]; e1 = e; }
        float p1 = expf(l1 - l0);
        float inv = 1.f / (1.f + p1);
        float w0 = inv, w1v = p1 * inv;
        int pos0 = atomicAdd(&g_cnt[e0], 1);
        int pos1 = atomicAdd(&g_cnt[e1], 1);
        g_gather[e0 * T_TOK + pos0] = t;
        g_gather[e1 * T_TOK + pos1] = t;
        g_etok[2 * t] = e0;  g_etok[2 * t + 1] = e1;
        g_ptok[2 * t] = pos0; g_ptok[2 * t + 1] = pos1;
        g_wtok[2 * t] = w0;  g_wtok[2 * t + 1] = w1v;
    }
}

// ---------------- grouped GEMM via mma.sync (HMMA path; tcgen05 rejected by
// compute_100 PTX target the harness uses) ----------------
// G1: h[rows, HID-tile] = relu( gathered_x[rows, DIM] @ w1[e]^T ), fp16 out
// G2: y[rows, DIM-tile] =        h[rows, HID]        @ w2[e]^T  , fp16 out
// CTA tile 128x128xK, 256 threads, warp grid 2(M) x 4(N), warp tile 64x32.
// Flat x-grid of exact m-blocks (g_boff mapping) -- no no-op CTA storm.
template <bool G1>
__global__ void __launch_bounds__(256, 2) moe_gemm_kernel() {
    constexpr int KTOT = G1 ? DIM : HID;
    constexpr int NCH  = KTOT / CHUNK_K;   // 8 or 32
    const int mb = blockIdx.x;
    if (mb >= g_boff[NEXP]) return;
    int e = 0;
#pragma unroll
    for (int k = 1; k < NEXP; k++) if (mb >= g_boff[k]) e = k;
    const int m0  = (mb - g_boff[e]) * TILE_M;
    const int cnt = g_cnt[e];
    const int off = g_off[e];
    const int nt0 = blockIdx.y * TILE_N;

    extern __shared__ char smem[];
    const uint32_t sb = smem_u32(smem);
    const int tid = threadIdx.x, wid = tid >> 5, lane = tid & 31;
    const int wm = wid & 1, wn = wid >> 1;              // warp coords: 2(M) x 4(N)

    const int valid = min(cnt - m0, TILE_M);

    // ---- load mapping: thread t -> row t/2, four 16B segments ----
    const int lr = tid >> 1;                            // 0..127
    const int sseg = (tid & 1) * 4;                     // 0 or 4
    const unsigned asz = (lr < valid) ? 16u : 0u;       // zero-fill invalid rows
    const int ar = min(lr, valid - 1);
    const char* aBase;
    if (G1) {
        int tok = g_gather[e * T_TOK + m0 + ar];
        aBase = (const char*)(g_xh + (size_t)tok * DIM);
    } else {
        aBase = (const char*)(g_h + (size_t)(off + m0 + ar) * HID);
    }
    const char* bBase = G1
        ? (const char*)(g_w1h + ((size_t)e * HID + nt0 + lr) * DIM)
        : (const char*)(g_w2h + ((size_t)e * DIM + nt0 + lr) * HID);
    const int rowoff = lr * 128;
    const int swr = (lr & 7);

    auto load_stage = [&](int stg, int ch) {
        uint32_t s0 = sb + stg * STAGE_B;
#pragma unroll
        for (int i = 0; i < 4; i++) {
            int s = sseg + i;
            uint32_t sw = rowoff + (((unsigned)(s ^ swr)) << 4);
            cpa16(s0 + sw,            aBase + ch * 128 + s * 16, asz);
            cpa16(s0 + ATILE_B + sw,  bBase + ch * 128 + s * 16, 16u);
        }
        asm volatile("cp.async.commit_group;" ::: "memory");
    };

#pragma unroll
    for (int i = 0; i < NSTAGE - 1; i++) load_stage(i, i);

    float acc[4][4][4];
#pragma unroll
    for (int a = 0; a < 4; a++)
#pragma unroll
        for (int b = 0; b < 4; b++)
#pragma unroll
            for (int c = 0; c < 4; c++) acc[a][b][c] = 0.f;

    // ldmatrix lane addressing
    const int arow = wm * 64 + (lane & 15);             // A row within tile
    const int akb  = (lane & 16);                       // +16B for k8..15 halves
    const int brow = wn * 32 + (lane & 7) + ((lane & 16) >> 1);
    const int bkb  = ((lane & 8) << 1);

    for (int i = 0; i < NCH; i++) {
        // stage i must be complete; stage i+1 may remain in flight.
        if (i == NCH - 1) asm volatile("cp.async.wait_group 0;" ::: "memory");
        else              asm volatile("cp.async.wait_group 1;" ::: "memory");
        __syncthreads();   // single barrier: data visible + prev stage's consumers done

        // issue loads for stage i+2 into the buffer freed by stage i-1
        {
            const int nxt = i + NSTAGE - 1;
            if (nxt < NCH) load_stage(nxt % NSTAGE, nxt);
        }

        const int s = i % NSTAGE;
        const uint32_t sA = sb + s * STAGE_B;
        const uint32_t sB = sA + ATILE_B;
#pragma unroll
        for (int ks = 0; ks < 4; ks++) {
            uint32_t afr[4][4], bfr[2][4];
            const uint32_t akbs = (ks * 32 + akb) ^ ((arow & 7) << 4);
#pragma unroll
            for (int mt = 0; mt < 4; mt++)
                ldsm4(afr[mt], sA + (arow + mt * 16) * 128 + akbs);
            const uint32_t bkbs = (ks * 32 + bkb) ^ ((brow & 7) << 4);
#pragma unroll
            for (int bt = 0; bt < 2; bt++)
                ldsm4(bfr[bt], sB + (brow + bt * 16) * 128 + bkbs);
#pragma unroll
            for (int mt = 0; mt < 4; mt++)
#pragma unroll
                for (int nt = 0; nt < 4; nt++)
                    mma16816(acc[mt][nt], afr[mt], &bfr[nt >> 1][(nt & 1) * 2]);
        }
    }

    // ---- epilogue ----
    const int qrow = lane >> 2, qcol = (lane & 3) * 2;
#pragma unroll
    for (int mt = 0; mt < 4; mt++) {
#pragma unroll
        for (int half = 0; half < 2; half++) {
            const int rl = wm * 64 + mt * 16 + qrow + half * 8;
            if (rl >= valid) continue;
            const size_t rg = (size_t)(off + m0 + rl);
#pragma unroll
            for (int nt = 0; nt < 4; nt++) {
                const int colg = nt0 + wn * 32 + nt * 8 + qcol;
                float v0 = acc[mt][nt][2 * half];
                float v1 = acc[mt][nt][2 * half + 1];
                if (G1) {
                    *(__half2*)(g_h + rg * HID + colg) =
                        __floats2half2_rn(fmaxf(v0, 0.f), fmaxf(v1, 0.f));
                } else {
                    *(__half2*)(g_y + rg * DIM + colg) = __floats2half2_rn(v0, v1);
                }
            }
        }
    }
}

// out[t] = w0 * y[row0] + w1 * y[row1]   (128 threads x 4 floats = 512 floats)
__global__ void combine_kernel(float* __restrict__ out) {
    int t = blockIdx.x;
    int e0 = g_etok[2 * t], e1 = g_etok[2 * t + 1];
    int r0 = g_off[e0] + g_ptok[2 * t];
    int r1 = g_off[e1] + g_ptok[2 * t + 1];
    float w0 = g_wtok[2 * t], w1 = g_wtok[2 * t + 1];
    int i = threadIdx.x;
    uint2 a = ((const uint2*)(g_y + (size_t)r0 * DIM))[i];   // 4 halfs
    uint2 b = ((const uint2*)(g_y + (size_t)r1 * DIM))[i];
    __half2 a0 = *(__half2*)&a.x, a1 = *(__half2*)&a.y;
    __half2 b0 = *(__half2*)&b.x, b1 = *(__half2*)&b.y;
    float4 o;
    o.x = w0 * __low2float(a0)  + w1 * __low2float(b0);
    o.y = w0 * __high2float(a0) + w1 * __high2float(b0);
    o.z = w0 * __low2float(a1)  + w1 * __low2float(b1);
    o.w = w0 * __high2float(a1) + w1 * __high2float(b1);
    ((float4*)(out + (size_t)t * DIM))[i] = o;
}

// ---------------- launch ----------------
extern "C" void kernel_launch(void* const* d_in, const int* in_sizes, int n_in,
                              void* d_out, int out_size) {
    const float* x  = (const float*)d_in[0];
    const float* gw = (const float*)d_in[1];
    const float* w1 = (const float*)d_in[2];
    const float* w2 = (const float*)d_in[3];
    float* out = (float*)d_out;

    cudaFuncSetAttribute(moe_gemm_kernel<true>,
                         cudaFuncAttributeMaxDynamicSharedMemorySize, SMEM_BYTES);
    cudaFuncSetAttribute(moe_gemm_kernel<false>,
                         cudaFuncAttributeMaxDynamicSharedMemorySize, SMEM_BYTES);

    init_kernel<<<1, 32>>>();
    prep_kernel<<<PREP_BLOCKS, 256>>>(x, gw, w1, w2);
    scan_kernel<<<1, 32>>>();
    moe_gemm_kernel<true ><<<dim3(MAXMB, HID / TILE_N, 1), 256, SMEM_BYTES>>>();
    moe_gemm_kernel<false><<<dim3(MAXMB, DIM / TILE_N, 1), 256, SMEM_BYTES>>>();
    combine_kernel<<<T_TOK, 128>>>(out);
}